// round 1
// baseline (speedup 1.0000x reference)
#include <cuda_runtime.h>

// Problem constants
#define BATCH 2048
#define MF    26      // fields
#define KE    32      // embedding k
#define H1N   128
#define H2N   128
#define C1    (MF*MF)   // 676
#define C2    (H1N*MF)  // 3328
#define OUTW  (H1N+H2N) // 256

// Device-global scratch (allocation-free rule: statics only)
__device__ float g_W1t[C1 * H1N];       // [c][h]  (c = i*26+j)
__device__ float g_S[BATCH * C2];       // [b][i*26+j], i in H1, j in MF

// ---------------------------------------------------------------------------
// K0: transpose W1[h][c] -> g_W1t[c][h]
// ---------------------------------------------------------------------------
__global__ void k_transpose_w1(const float* __restrict__ W1) {
    int idx = blockIdx.x * blockDim.x + threadIdx.x;
    if (idx < C1 * H1N) {
        int h = idx & (H1N - 1);
        int c = idx >> 7;
        g_W1t[idx] = W1[h * C1 + c];
    }
}

// ---------------------------------------------------------------------------
// K1: per-batch fused layer1 + out1 + S
//   block = one b, 128 threads.
//   thread t: hg = t&15 -> h in [8*hg, 8*hg+8); kq = t>>4 -> k in [4*kq, 4*kq+4)
//   x1[h][k] = sum_c W1t[c][h] * x0[i][k]*x0[j][k]   (c = i*26+j)
//   f32x2: lanes are adjacent h (w-pairs load directly as 64-bit from smem).
// ---------------------------------------------------------------------------
__global__ __launch_bounds__(128) void k_layer1(
    const float* __restrict__ x0g,
    const float* __restrict__ b1,
    float* __restrict__ out)
{
    __shared__ float xs[MF][KE];          // 26x32 input slice
    __shared__ float w1s[MF][H1N];        // one i-row of W1t: 26 j x 128 h
    __shared__ float x1s[H1N][KE + 1];    // padded to kill bank conflicts

    const int b  = blockIdx.x;
    const int t  = threadIdx.x;
    const int hg = t & 15;    // h base = 8*hg
    const int kq = t >> 4;    // k base = 4*kq

    const float* x0 = x0g + (size_t)b * MF * KE;

    // load x0 slice
    for (int idx = t; idx < MF * KE; idx += 128)
        xs[idx / KE][idx % KE] = x0[idx];

    // accumulators: 4 h-pairs x 4 k, packed f32x2 (lo = even h, hi = odd h)
    unsigned long long acc[4][4];
#pragma unroll
    for (int r = 0; r < 4; r++)
#pragma unroll
        for (int q = 0; q < 4; q++) acc[r][q] = 0ULL;

    for (int i = 0; i < MF; i++) {
        __syncthreads();
        // stage W1t rows c = i*26 .. i*26+25 (26*128 floats = 832 float4)
        {
            const float4* src = reinterpret_cast<const float4*>(g_W1t + i * MF * H1N);
            float4* dst = reinterpret_cast<float4*>(&w1s[0][0]);
            for (int idx = t; idx < (MF * H1N) / 4; idx += 128) dst[idx] = src[idx];
        }
        __syncthreads();

        float xi[4];
#pragma unroll
        for (int q = 0; q < 4; q++) xi[q] = xs[i][4 * kq + q];

#pragma unroll 2
        for (int j = 0; j < MF; j++) {
            float4 xjv = *reinterpret_cast<const float4*>(&xs[j][4 * kq]);
            // 8 consecutive h values as 4 f32x2 pairs
            ulonglong2 w01 = *reinterpret_cast<const ulonglong2*>(&w1s[j][8 * hg]);
            ulonglong2 w23 = *reinterpret_cast<const ulonglong2*>(&w1s[j][8 * hg + 4]);
            unsigned long long wv[4] = {w01.x, w01.y, w23.x, w23.y};
            const float* xjp = &xjv.x;
#pragma unroll
            for (int q = 0; q < 4; q++) {
                float p = xi[q] * xjp[q];
                unsigned long long p2;
                asm("mov.b64 %0, {%1, %1};" : "=l"(p2) : "f"(p));
#pragma unroll
                for (int r = 0; r < 4; r++)
                    asm("fma.rn.f32x2 %0, %1, %2, %0;"
                        : "+l"(acc[r][q]) : "l"(wv[r]), "l"(p2));
            }
        }
    }

    // add bias, write x1 to smem
    float2 bias[4];
#pragma unroll
    for (int r = 0; r < 4; r++)
        bias[r] = reinterpret_cast<const float2*>(b1)[4 * hg + r];

#pragma unroll
    for (int r = 0; r < 4; r++) {
        int h = 8 * hg + 2 * r;
#pragma unroll
        for (int q = 0; q < 4; q++) {
            float2 v = *reinterpret_cast<float2*>(&acc[r][q]);
            x1s[h][4 * kq + q]     = v.x + bias[r].x;
            x1s[h + 1][4 * kq + q] = v.y + bias[r].y;
        }
    }
    __syncthreads();

    // out1[b][h] = sum_k x1[h][k]
    {
        int h = t;  // 0..127
        float s = 0.f;
#pragma unroll
        for (int k = 0; k < KE; k++) s += x1s[h][k];
        out[(size_t)b * OUTW + h] = s;
    }

    // S[b][i2][j2] = sum_k x1[i2][k] * x0[j2][k]
    {
        int i2 = t;  // 0..127
        float* Srow = g_S + (size_t)b * C2 + i2 * MF;
        for (int j2 = 0; j2 < MF; j2++) {
            float s = 0.f;
#pragma unroll
            for (int k = 0; k < KE; k++) s += x1s[i2][k] * xs[j2][k];
            Srow[j2] = s;
        }
    }
}

// ---------------------------------------------------------------------------
// K2: out2[b][h] = sum_c S[b][c] * W2[h][c] + 32*b2[h]
//   GEMM M=2048, N=128, K=3328. Tile 32(b) x 64(h), grid (64,2)=128 blocks,
//   256 threads, 8 outputs/thread (2 b x 4 h).
// ---------------------------------------------------------------------------
#define KC 32
__global__ __launch_bounds__(256) void k_out2(
    const float* __restrict__ W2,
    const float* __restrict__ b2,
    float* __restrict__ out)
{
    __shared__ float St[32][KC + 1];
    __shared__ float Wt[64][KC + 1];

    const int t  = threadIdx.x;
    const int tx = t & 15;   // h group: h_local = 4*tx
    const int ty = t >> 4;   // b group: b_local = 2*ty + {0,1}
    const int b0 = blockIdx.x * 32;
    const int h0 = blockIdx.y * 64;

    float acc[2][4] = {{0.f, 0.f, 0.f, 0.f}, {0.f, 0.f, 0.f, 0.f}};

    for (int kc = 0; kc < C2; kc += KC) {
        // load S tile: 32 rows x 32 cols = 256 float4, 1 per thread
        {
            int row = t >> 3;
            int c4  = t & 7;
            float4 v = *reinterpret_cast<const float4*>(
                g_S + (size_t)(b0 + row) * C2 + kc + 4 * c4);
            St[row][4 * c4 + 0] = v.x;
            St[row][4 * c4 + 1] = v.y;
            St[row][4 * c4 + 2] = v.z;
            St[row][4 * c4 + 3] = v.w;
        }
        // load W2 tile: 64 rows x 32 cols = 512 float4, 2 per thread
#pragma unroll
        for (int l = 0; l < 2; l++) {
            int lin = t + 256 * l;
            int row = lin >> 3;
            int c4  = lin & 7;
            float4 v = *reinterpret_cast<const float4*>(
                W2 + (size_t)(h0 + row) * C2 + kc + 4 * c4);
            Wt[row][4 * c4 + 0] = v.x;
            Wt[row][4 * c4 + 1] = v.y;
            Wt[row][4 * c4 + 2] = v.z;
            Wt[row][4 * c4 + 3] = v.w;
        }
        __syncthreads();

#pragma unroll 8
        for (int kk = 0; kk < KC; kk++) {
            float a0 = St[2 * ty + 0][kk];
            float a1 = St[2 * ty + 1][kk];
            float w0 = Wt[4 * tx + 0][kk];
            float w1 = Wt[4 * tx + 1][kk];
            float w2 = Wt[4 * tx + 2][kk];
            float w3 = Wt[4 * tx + 3][kk];
            acc[0][0] += a0 * w0; acc[0][1] += a0 * w1;
            acc[0][2] += a0 * w2; acc[0][3] += a0 * w3;
            acc[1][0] += a1 * w0; acc[1][1] += a1 * w1;
            acc[1][2] += a1 * w2; acc[1][3] += a1 * w3;
        }
        __syncthreads();
    }

#pragma unroll
    for (int r = 0; r < 4; r++) {
        int h = h0 + 4 * tx + r;
        float bias = (float)KE * b2[h];
#pragma unroll
        for (int d = 0; d < 2; d++) {
            int b = b0 + 2 * ty + d;
            out[(size_t)b * OUTW + H1N + h] = acc[d][r] + bias;
        }
    }
}

// ---------------------------------------------------------------------------
// launch
// ---------------------------------------------------------------------------
extern "C" void kernel_launch(void* const* d_in, const int* in_sizes, int n_in,
                              void* d_out, int out_size) {
    const float* inputs = (const float*)d_in[0];  // [2048,26,32]
    const float* W1     = (const float*)d_in[1];  // [128,26,26]
    const float* b1     = (const float*)d_in[2];  // [128]
    const float* W2     = (const float*)d_in[3];  // [128,128,26]
    const float* b2     = (const float*)d_in[4];  // [128]
    float* out = (float*)d_out;                   // [2048,256]

    // K0: transpose W1 into [c][h]
    k_transpose_w1<<<(C1 * H1N + 255) / 256, 256>>>(W1);

    // K1: layer1 + out1 + S
    k_layer1<<<BATCH, 128>>>(inputs, b1, out);

    // K2: out2 GEMM
    dim3 g2(BATCH / 32, H2N / 64);
    k_out2<<<g2, 256>>>(W2, b2, out);
}

// round 2
// speedup vs baseline: 2.0625x; 2.0625x over previous
#include <cuda_runtime.h>

// Problem constants
#define BATCH 2048
#define MF    26          // fields
#define KE    32          // embedding k
#define H1N   128
#define H2N   128
#define C1    (MF*MF)     // 676
#define NPAIR 351         // MF*(MF+1)/2 symmetric pairs
#define C2    (H1N*MF)    // 3328
#define OUTW  (H1N+H2N)   // 256

typedef unsigned long long ull;

// Device-global scratch (allocation-free rule: statics only)
__device__ float g_W1t[NPAIR * H1N];   // symmetrized, h-chunk-permuted: [pair][perm(h)]
__device__ float g_S[BATCH * C2];      // [b][i*26+j], i in H1 index, j in MF

#define FMA2(a, x, y) asm("fma.rn.f32x2 %0, %1, %2, %0;" : "+l"(a) : "l"(x), "l"(y))
#define MUL2(d, x, y) asm("mul.rn.f32x2 %0, %1, %2;" : "=l"(d) : "l"(x), "l"(y))
#define ADD2(a, x)    asm("add.rn.f32x2 %0, %0, %1;" : "+l"(a) : "l"(x))
#define DUP2(d, f)    asm("mov.b64 %0, {%1, %1};" : "=l"(d) : "f"(f))

// ---------------------------------------------------------------------------
// K0: build symmetrized, permuted W1'.
//   pair p enumerates (i, j>=i) in i-major order.
//   W'[p][h] = W1[h,i,j] + W1[h,j,i]  (j>i),  W1[h,i,i]  (j==i)
//   h permutation: chunk c = h/4 -> slot ((c&1)*16 + (c>>1)), preserving h%4.
//   This makes the per-thread 16B w loads in k_layer1 bank-conflict-free.
// ---------------------------------------------------------------------------
__global__ void k_prep_w1(const float* __restrict__ W1) {
    int idx = blockIdx.x * blockDim.x + threadIdx.x;
    if (idx >= NPAIR * H1N) return;
    int p  = idx >> 7;
    int hh = idx & 127;
    // invert triangular index
    int i = 0, off = 0;
    while (p >= off + (MF - i)) { off += MF - i; i++; }
    int j = i + (p - off);
    float v;
    if (i == j) v = W1[hh * C1 + i * MF + i];
    else        v = W1[hh * C1 + i * MF + j] + W1[hh * C1 + j * MF + i];
    int c = hh >> 2;
    int pos = ((c & 1) << 4) | (c >> 1);
    g_W1t[p * H1N + pos * 4 + (hh & 3)] = v;
}

// ---------------------------------------------------------------------------
// K1: fused layer1 (symmetric form) + out1 + S.  Block = 2 batches, 128 thr.
//   thread t: hg = t&15 (8 h: 8hg..8hg+7), kq = (t>>4)&3 (8 k: 8kq..), bsel = t>>6
//   acc[r][q]: r = h-pair (8hg+2r, 8hg+2r+1), q = k offset (8kq+q), f32x2 over h
// ---------------------------------------------------------------------------
__global__ __launch_bounds__(128, 3) void k_layer1(
    const float* __restrict__ x0g,
    const float* __restrict__ b1,
    float* __restrict__ out)
{
    __shared__ float xs[2 * MF * KE];        // 1664 floats, layout [bs][field][k]
    __shared__ float pool[2 * H1N * 34];     // x1s [bs][h][34]; reused as w1s in loop

    const int t    = threadIdx.x;
    const int hg   = t & 15;
    const int kq   = (t >> 4) & 3;
    const int bsel = t >> 6;
    const int b0   = blockIdx.x * 2;

    // load both batches' x0 (contiguous 1664 floats)
    {
        const float4* src = reinterpret_cast<const float4*>(x0g + (size_t)b0 * MF * KE);
        float4* dst = reinterpret_cast<float4*>(xs);
        for (int idx = t; idx < (2 * MF * KE) / 4; idx += 128) dst[idx] = src[idx];
    }

    ull acc[4][8];
#pragma unroll
    for (int r = 0; r < 4; r++)
#pragma unroll
        for (int q = 0; q < 8; q++) acc[r][q] = 0ULL;

    float* w1s = pool;
    const float* xrow_base = xs + (bsel * MF) * KE;

    int off = 0;
    for (int i = 0; i < MF; i++) {
        int nrows = MF - i;
        __syncthreads();
        {
            const float4* src = reinterpret_cast<const float4*>(g_W1t + (size_t)off * H1N);
            float4* dst = reinterpret_cast<float4*>(w1s);
            int n4 = nrows * (H1N / 4);
            for (int idx = t; idx < n4; idx += 128) dst[idx] = src[idx];
        }
        __syncthreads();

        // xi (k = 8kq .. 8kq+7) as 4 f32x2 (k-pairs)
        ull xi2[4];
        {
            ulonglong2 v0 = *reinterpret_cast<const ulonglong2*>(xrow_base + i * KE + 8 * kq);
            ulonglong2 v1 = *reinterpret_cast<const ulonglong2*>(xrow_base + i * KE + 8 * kq + 4);
            xi2[0] = v0.x; xi2[1] = v0.y; xi2[2] = v1.x; xi2[3] = v1.y;
        }

        for (int jj = 0; jj < nrows; jj++) {
            int j = i + jj;
            ull xj2[4];
            {
                ulonglong2 v0 = *reinterpret_cast<const ulonglong2*>(xrow_base + j * KE + 8 * kq);
                ulonglong2 v1 = *reinterpret_cast<const ulonglong2*>(xrow_base + j * KE + 8 * kq + 4);
                xj2[0] = v0.x; xj2[1] = v0.y; xj2[2] = v1.x; xj2[3] = v1.y;
            }
            // w pairs for h = 8hg..8hg+7 (permuted layout: conflict-free 16B loads)
            ulonglong2 wl = *reinterpret_cast<const ulonglong2*>(w1s + jj * H1N + hg * 4);
            ulonglong2 wh = *reinterpret_cast<const ulonglong2*>(w1s + jj * H1N + 64 + hg * 4);
            ull wp0 = wl.x, wp1 = wl.y, wp2 = wh.x, wp3 = wh.y;

#pragma unroll
            for (int v = 0; v < 4; v++) {
                ull pk;
                MUL2(pk, xi2[v], xj2[v]);
                float2 pf = *reinterpret_cast<float2*>(&pk);
                ull d0, d1;
                DUP2(d0, pf.x);
                DUP2(d1, pf.y);
                FMA2(acc[0][2 * v],     wp0, d0);
                FMA2(acc[1][2 * v],     wp1, d0);
                FMA2(acc[2][2 * v],     wp2, d0);
                FMA2(acc[3][2 * v],     wp3, d0);
                FMA2(acc[0][2 * v + 1], wp0, d1);
                FMA2(acc[1][2 * v + 1], wp1, d1);
                FMA2(acc[2][2 * v + 1], wp2, d1);
                FMA2(acc[3][2 * v + 1], wp3, d1);
            }
        }
        off += nrows;
    }

    __syncthreads();   // all warps done reading w1s; pool becomes x1s

    // add bias, write x1 (pad-34 rows)
#pragma unroll
    for (int r = 0; r < 4; r++) {
        int h = 8 * hg + 2 * r;
        float2 bv = reinterpret_cast<const float2*>(b1)[4 * hg + r];
        float* row0 = pool + (size_t)(bsel * H1N + h) * 34 + 8 * kq;
        float* row1 = row0 + 34;
#pragma unroll
        for (int q = 0; q < 8; q++) {
            float2 av = *reinterpret_cast<float2*>(&acc[r][q]);
            row0[q] = av.x + bv.x;
            row1[q] = av.y + bv.y;
        }
    }
    __syncthreads();

    // epilogue per batch: out1[h=t] and S[t][0..25]
    for (int bs = 0; bs < 2; bs++) {
        ull xr2[16];
        const float* x1row = pool + (size_t)(bs * H1N + t) * 34;
#pragma unroll
        for (int kp = 0; kp < 16; kp++)
            xr2[kp] = *reinterpret_cast<const ull*>(x1row + 2 * kp);

        // out1 = sum_k x1[t][k]
        ull s2 = 0ULL;
#pragma unroll
        for (int kp = 0; kp < 16; kp++) ADD2(s2, xr2[kp]);
        float2 sf = *reinterpret_cast<float2*>(&s2);
        out[(size_t)(b0 + bs) * OUTW + t] = sf.x + sf.y;

        // S[b][t*26 + j2] = sum_k x1[t][k] * x0[j2][k]
        const float* xb = xs + (size_t)bs * MF * KE;
        float* Srow = g_S + (size_t)(b0 + bs) * C2 + t * MF;
        for (int j2 = 0; j2 < MF; j2++) {
            ull a2 = 0ULL;
            const float* xj = xb + j2 * KE;
#pragma unroll
            for (int kp = 0; kp < 16; kp++) {
                ull xp = *reinterpret_cast<const ull*>(xj + 2 * kp);
                FMA2(a2, xr2[kp], xp);
            }
            float2 af = *reinterpret_cast<float2*>(&a2);
            Srow[j2] = af.x + af.y;
        }
    }
}

// ---------------------------------------------------------------------------
// K2: out2[b][h] = sum_c S[b][c]*W2[h][c] + 32*b2[h]
//   GEMM M=2048 N=128 K=3328. Tile 32b x 64h, grid (64,2), 256 thr.
//   Tiles stored transposed in smem ([kk][b] / [kk][h]) for vector LDS.
//   thread: tx = t&15 -> 4 h (4tx..), ty = t>>4 -> 2 b (2ty..), f32x2 over h.
// ---------------------------------------------------------------------------
#define KC 32
__global__ __launch_bounds__(256) void k_out2(
    const float* __restrict__ W2,
    const float* __restrict__ b2,
    float* __restrict__ out)
{
    __shared__ float Sts[KC][34];   // [kk][b-local]
    __shared__ float Wts[KC][68];   // [kk][h-local]

    const int t  = threadIdx.x;
    const int tx = t & 15;
    const int ty = t >> 4;
    const int b0 = blockIdx.x * 32;
    const int h0 = blockIdx.y * 64;

    ull acc[2][2] = {{0ULL, 0ULL}, {0ULL, 0ULL}};

    const int srow = t >> 3;
    const int sc4  = t & 7;

    for (int kc = 0; kc < C2; kc += KC) {
        __syncthreads();
        // stage S tile transposed: 32 rows x 32 cols
        {
            float4 v = *reinterpret_cast<const float4*>(
                g_S + (size_t)(b0 + srow) * C2 + kc + 4 * sc4);
            Sts[4 * sc4 + 0][srow] = v.x;
            Sts[4 * sc4 + 1][srow] = v.y;
            Sts[4 * sc4 + 2][srow] = v.z;
            Sts[4 * sc4 + 3][srow] = v.w;
        }
        // stage W tile transposed: 64 rows x 32 cols
#pragma unroll
        for (int l = 0; l < 2; l++) {
            int lin = t + 256 * l;
            int row = lin >> 3;
            int c4  = lin & 7;
            float4 v = *reinterpret_cast<const float4*>(
                W2 + (size_t)(h0 + row) * C2 + kc + 4 * c4);
            Wts[4 * c4 + 0][row] = v.x;
            Wts[4 * c4 + 1][row] = v.y;
            Wts[4 * c4 + 2][row] = v.z;
            Wts[4 * c4 + 3][row] = v.w;
        }
        __syncthreads();

#pragma unroll 8
        for (int kk = 0; kk < KC; kk++) {
            float2 a = *reinterpret_cast<const float2*>(&Sts[kk][2 * ty]);
            ulonglong2 w = *reinterpret_cast<const ulonglong2*>(&Wts[kk][4 * tx]);
            ull d0, d1;
            DUP2(d0, a.x);
            DUP2(d1, a.y);
            FMA2(acc[0][0], w.x, d0);
            FMA2(acc[0][1], w.y, d0);
            FMA2(acc[1][0], w.x, d1);
            FMA2(acc[1][1], w.y, d1);
        }
    }

#pragma unroll
    for (int d = 0; d < 2; d++) {
        int b = b0 + 2 * ty + d;
#pragma unroll
        for (int p = 0; p < 2; p++) {
            float2 v = *reinterpret_cast<float2*>(&acc[d][p]);
            int h = h0 + 4 * tx + 2 * p;
            out[(size_t)b * OUTW + H1N + h]     = v.x + (float)KE * b2[h];
            out[(size_t)b * OUTW + H1N + h + 1] = v.y + (float)KE * b2[h + 1];
        }
    }
}

// ---------------------------------------------------------------------------
// launch
// ---------------------------------------------------------------------------
extern "C" void kernel_launch(void* const* d_in, const int* in_sizes, int n_in,
                              void* d_out, int out_size) {
    const float* inputs = (const float*)d_in[0];  // [2048,26,32]
    const float* W1     = (const float*)d_in[1];  // [128,26,26]
    const float* b1     = (const float*)d_in[2];  // [128]
    const float* W2     = (const float*)d_in[3];  // [128,128,26]
    const float* b2     = (const float*)d_in[4];  // [128]
    float* out = (float*)d_out;                   // [2048,256]

    k_prep_w1<<<(NPAIR * H1N + 255) / 256, 256>>>(W1);
    k_layer1<<<BATCH / 2, 128>>>(inputs, b1, out);
    dim3 g2(BATCH / 32, H2N / 64);
    k_out2<<<g2, 256>>>(W2, b2, out);
}

// round 3
// speedup vs baseline: 3.4200x; 1.6582x over previous
#include <cuda_runtime.h>

#define BATCH 2048
#define MF    26
#define KE    32
#define H1N   128
#define H2N   128
#define C1    (MF*MF)       // 676
#define NPAIR 351           // p<=q pairs
#define NTRI  3276          // p<=q<=j multisets
#define NJ    3328          // 26*128
#define OUTW  256
#define FSTR  3712          // F row stride: [G 0..350 |pad| T 352..3627 | sx 3628..3653 | pad..3711]

typedef unsigned long long ull;

// device-global scratch
__device__ int   g_pqtab[NPAIR];            // p | q<<8
__device__ int   g_e2pqj[NTRI];             // p | q<<8 | j<<16
__device__ float g_W1s[352 * 128];          // [pq][i], row 351 = 0
__device__ float g_W2t[128 * NJ];           // [i][j*128+h]
__device__ float g_U[352 * NJ];             // [pq][j*128+h]
__device__ float g_Up[NJ * 128];            // U'' rows: 0..3275 U', 3276..3301 v, rest 0
__device__ float g_F[BATCH * FSTR];         // features
__device__ float g_part[2][BATCH * 128];    // out2 k-split partials

#define FMA2(a, x, y) asm("fma.rn.f32x2 %0, %1, %2, %0;" : "+l"(a) : "l"(x), "l"(y))
#define MUL2(d, x, y) asm("mul.rn.f32x2 %0, %1, %2;" : "=l"(d) : "l"(x), "l"(y))
#define ADD2(a, x)    asm("add.rn.f32x2 %0, %0, %1;" : "+l"(a) : "l"(x))
#define DUP2(d, f)    asm("mov.b64 %0, {%1, %1};" : "=l"(d) : "f"(f))

__device__ __forceinline__ int pqidx(int p, int q) {
    return p * MF - (p * (p - 1)) / 2 + (q - p);
}

// ---------------------------------------------------------------------------
// K_idx: build pair table and entry->(p,q,j) table.
// ---------------------------------------------------------------------------
__global__ void k_idx() {
    int pq = threadIdx.x;
    if (pq >= NPAIR) return;
    int p = 0, off = 0;
    while (pq >= off + (MF - p)) { off += MF - p; p++; }
    int q = p + (pq - off);
    g_pqtab[pq] = p | (q << 8);
    int mo = 0;
    for (int pp = 0; pp < p; pp++) mo += (MF - pp) * (MF - pp + 1) / 2;
    for (int qq = p; qq < q; qq++) mo += MF - qq;
    for (int dj = 0; dj < MF - q; dj++)
        g_e2pqj[mo + dj] = p | (q << 8) | ((q + dj) << 16);
}

// ---------------------------------------------------------------------------
// K_w1s: W1s[pq][i] = W1[i,p,q] + W1[i,q,p] (p<q), W1[i,p,p] (p==q); row 351 = 0
// ---------------------------------------------------------------------------
__global__ void k_w1s(const float* __restrict__ W1) {
    int gid = blockIdx.x * blockDim.x + threadIdx.x;   // 352*128
    int pq = gid >> 7, i = gid & 127;
    float v = 0.f;
    if (pq < NPAIR) {
        int pk = g_pqtab[pq];
        int p = pk & 255, q = (pk >> 8) & 255;
        v = W1[i * C1 + p * MF + q];
        if (p < q) v += W1[i * C1 + q * MF + p];
    }
    g_W1s[pq * 128 + i] = v;
}

// ---------------------------------------------------------------------------
// K_w2t: g_W2t[i][j*128+h] = W2[h][i][j]
// ---------------------------------------------------------------------------
__global__ void k_w2t(const float* __restrict__ W2) {
    int gid = blockIdx.x * blockDim.x + threadIdx.x;   // 128*3328
    int i = gid / NJ;
    int r = gid - i * NJ;
    int j = r >> 7, h = r & 127;
    g_W2t[gid] = W2[(size_t)h * NJ + i * MF + j];
}

// ---------------------------------------------------------------------------
// K_u: GEMM  g_U[pq][n] = sum_i g_W1s[pq][i] * g_W2t[i][n]
//   M=352, N=3328, K=128. Tile 32m x 64n, 256 thr, grid (11,52).
// ---------------------------------------------------------------------------
__global__ __launch_bounds__(256) void k_u() {
    __shared__ float Ats[32][36];   // [kk][m]
    __shared__ float Bs[32][64];    // [kk][n]
    const int t = threadIdx.x;
    const int tx = t & 15;          // n = 4*tx
    const int ty = t >> 4;          // m = 2*ty
    const int m0 = blockIdx.x * 32;
    const int n0 = blockIdx.y * 64;

    ull acc[2][2] = {{0ULL, 0ULL}, {0ULL, 0ULL}};

    for (int kc = 0; kc < 128; kc += 32) {
        __syncthreads();
        {   // A tile 32m x 32k
            int row = t >> 3, c4 = t & 7;
            float4 v = *reinterpret_cast<const float4*>(
                g_W1s + (size_t)(m0 + row) * 128 + kc + 4 * c4);
            Ats[4 * c4 + 0][row] = v.x;
            Ats[4 * c4 + 1][row] = v.y;
            Ats[4 * c4 + 2][row] = v.z;
            Ats[4 * c4 + 3][row] = v.w;
        }
#pragma unroll
        for (int l = 0; l < 2; l++) {  // B tile 32k x 64n
            int idx = t + 256 * l;
            int row = idx >> 4, c4 = idx & 15;
            *reinterpret_cast<float4*>(&Bs[row][4 * c4]) =
                *reinterpret_cast<const float4*>(g_W2t + (size_t)(kc + row) * NJ + n0 + 4 * c4);
        }
        __syncthreads();

#pragma unroll
        for (int kk = 0; kk < 32; kk++) {
            float2 a = *reinterpret_cast<const float2*>(&Ats[kk][2 * ty]);
            ulonglong2 w = *reinterpret_cast<const ulonglong2*>(&Bs[kk][4 * tx]);
            ull d;
            DUP2(d, a.x);
            FMA2(acc[0][0], w.x, d); FMA2(acc[0][1], w.y, d);
            DUP2(d, a.y);
            FMA2(acc[1][0], w.x, d); FMA2(acc[1][1], w.y, d);
        }
    }
#pragma unroll
    for (int dm = 0; dm < 2; dm++) {
        float* dst = g_U + (size_t)(m0 + 2 * ty + dm) * NJ + n0 + 4 * tx;
        *reinterpret_cast<float2*>(dst)     = *reinterpret_cast<float2*>(&acc[dm][0]);
        *reinterpret_cast<float2*>(dst + 2) = *reinterpret_cast<float2*>(&acc[dm][1]);
    }
}

// ---------------------------------------------------------------------------
// K_fold: build U''[e][h]:
//   e<3276:  fold of U over multiset permutations
//   3276..3301: v[j][h] = sum_i b1[i]*W2t[i][j*128+h]
//   3302..3327: 0
// ---------------------------------------------------------------------------
__global__ void k_fold(const float* __restrict__ b1) {
    int gid = blockIdx.x * blockDim.x + threadIdx.x;   // 3328*128
    int e = gid >> 7, h = gid & 127;
    float val = 0.f;
    if (e < NTRI) {
        int c = g_e2pqj[e];
        int p = c & 255, q = (c >> 8) & 255, j = (c >> 16) & 255;
        #define CU(PQ, J) g_U[(size_t)(PQ) * NJ + (J) * 128 + h]
        if (p < q) {
            if (q < j)      val = CU(pqidx(p,q), j) + CU(pqidx(p,j), q) + CU(pqidx(q,j), p);
            else            val = CU(pqidx(p,q), q) + CU(pqidx(q,q), p);   // q==j
        } else {            // p==q
            if (q < j)      val = CU(pqidx(p,p), j) + CU(pqidx(p,j), p);
            else            val = CU(pqidx(p,p), p);                        // p==q==j
        }
        #undef CU
    } else if (e < NTRI + MF) {
        int j = e - NTRI;
        float s = 0.f;
        for (int i = 0; i < 128; i++)
            s += b1[i] * g_W2t[(size_t)i * NJ + j * 128 + h];
        val = s;
    }
    g_Up[(size_t)e * 128 + h] = val;
}

// ---------------------------------------------------------------------------
// K_feat: per-batch features. Block = 1 b, 384 threads.
//   xs2[kp][j] = (x[j][2kp], x[j][2kp+1]) packed f32x2.
//   G[pq] = sum_k x_p x_q  -> F[0..350]
//   T[e]  = sum_k x_p x_q x_j (e enumerates p<=q<=j) -> F[352+e]
//   sx[j] = sum_k x_j -> F[3628+j];  pads zeroed.
// ---------------------------------------------------------------------------
#define EPT 9   // entries per thread: 384*9 >= 3276
__global__ __launch_bounds__(384) void k_feat(const float* __restrict__ x0g) {
    __shared__ ull xs2[16][33];
    const int b = blockIdx.x;
    const int t = threadIdx.x;

    for (int idx = t; idx < MF * 16; idx += 384) {
        int j = idx >> 4, kp = idx & 15;
        xs2[kp][j] = *reinterpret_cast<const ull*>(x0g + (size_t)b * MF * KE + j * KE + 2 * kp);
    }
    __syncthreads();

    float* F = g_F + (size_t)b * FSTR;

    if (t < 58) F[3654 + t] = 0.f;
    if (t == 351) F[351] = 0.f;

    // G
    if (t < NPAIR) {
        int pk = g_pqtab[t];
        int p = pk & 255, q = (pk >> 8) & 255;
        ull s0 = 0, s1 = 0, s2 = 0, s3 = 0;
#pragma unroll
        for (int kp = 0; kp < 16; kp += 4) {
            FMA2(s0, xs2[kp + 0][p], xs2[kp + 0][q]);
            FMA2(s1, xs2[kp + 1][p], xs2[kp + 1][q]);
            FMA2(s2, xs2[kp + 2][p], xs2[kp + 2][q]);
            FMA2(s3, xs2[kp + 3][p], xs2[kp + 3][q]);
        }
        ADD2(s0, s1); ADD2(s2, s3); ADD2(s0, s2);
        float2 sf = *reinterpret_cast<float2*>(&s0);
        F[t] = sf.x + sf.y;
    }

    // sx
    if (t < MF) {
        ull s0 = 0, s1 = 0;
#pragma unroll
        for (int kp = 0; kp < 16; kp += 2) {
            ADD2(s0, xs2[kp][t]);
            ADD2(s1, xs2[kp + 1][t]);
        }
        ADD2(s0, s1);
        float2 sf = *reinterpret_cast<float2*>(&s0);
        F[3628 + t] = sf.x + sf.y;
    }

    // T entries
    int e0 = t * EPT;
    int e1 = e0 + EPT; if (e1 > NTRI) e1 = NTRI;
    int curpq = -1;
    ull xx[16];
    for (int e = e0; e < e1; e++) {
        int c = g_e2pqj[e];
        int p = c & 255, q = (c >> 8) & 255, j = (c >> 16) & 255;
        if ((c & 0xFFFF) != curpq) {
            curpq = c & 0xFFFF;
#pragma unroll
            for (int kp = 0; kp < 16; kp++)
                MUL2(xx[kp], xs2[kp][p], xs2[kp][q]);
        }
        ull a0 = 0, a1 = 0, a2 = 0, a3 = 0;
#pragma unroll
        for (int kp = 0; kp < 16; kp += 4) {
            FMA2(a0, xx[kp + 0], xs2[kp + 0][j]);
            FMA2(a1, xx[kp + 1], xs2[kp + 1][j]);
            FMA2(a2, xx[kp + 2], xs2[kp + 2][j]);
            FMA2(a3, xx[kp + 3], xs2[kp + 3][j]);
        }
        ADD2(a0, a1); ADD2(a2, a3); ADD2(a0, a2);
        float2 af = *reinterpret_cast<float2*>(&a0);
        F[352 + e] = af.x + af.y;
    }
}

// ---------------------------------------------------------------------------
// K_out1: out[:,0:128] = F[:,0:352] @ W1s + 32*b1.  Tile 16b x 128h, grid 128.
// ---------------------------------------------------------------------------
__global__ __launch_bounds__(256) void k_out1(const float* __restrict__ b1,
                                              float* __restrict__ out) {
    __shared__ float As[32][20];    // [kk][b]
    __shared__ float Ws[32][128];   // [kk][h]
    const int t = threadIdx.x;
    const int tx = t & 31;   // h = 4*tx
    const int ty = t >> 5;   // b = 2*ty + d
    const int b0 = blockIdx.x * 16;

    ull acc[2][2] = {{0ULL, 0ULL}, {0ULL, 0ULL}};

    for (int kc = 0; kc < 352; kc += 32) {
        __syncthreads();
        if (t < 128) {
            int row = t >> 3, c4 = t & 7;
            float4 v = *reinterpret_cast<const float4*>(
                g_F + (size_t)(b0 + row) * FSTR + kc + 4 * c4);
            As[4 * c4 + 0][row] = v.x;
            As[4 * c4 + 1][row] = v.y;
            As[4 * c4 + 2][row] = v.z;
            As[4 * c4 + 3][row] = v.w;
        }
#pragma unroll
        for (int l = 0; l < 4; l++) {
            int idx = t + 256 * l;
            int row = idx >> 5, c4 = idx & 31;
            reinterpret_cast<float4*>(&Ws[row][0])[c4] =
                reinterpret_cast<const float4*>(g_W1s + (size_t)(kc + row) * 128)[c4];
        }
        __syncthreads();

#pragma unroll
        for (int kk = 0; kk < 32; kk++) {
            float2 a = *reinterpret_cast<const float2*>(&As[kk][2 * ty]);
            ulonglong2 w = *reinterpret_cast<const ulonglong2*>(&Ws[kk][4 * tx]);
            ull d;
            DUP2(d, a.x);
            FMA2(acc[0][0], w.x, d); FMA2(acc[0][1], w.y, d);
            DUP2(d, a.y);
            FMA2(acc[1][0], w.x, d); FMA2(acc[1][1], w.y, d);
        }
    }

    float4 bv = *reinterpret_cast<const float4*>(b1 + 4 * tx);
#pragma unroll
    for (int d = 0; d < 2; d++) {
        float2 v0 = *reinterpret_cast<float2*>(&acc[d][0]);
        float2 v1 = *reinterpret_cast<float2*>(&acc[d][1]);
        float4 o;
        o.x = v0.x + 32.f * bv.x;
        o.y = v0.y + 32.f * bv.y;
        o.z = v1.x + 32.f * bv.z;
        o.w = v1.y + 32.f * bv.w;
        *reinterpret_cast<float4*>(out + (size_t)(b0 + 2 * ty + d) * OUTW + 4 * tx) = o;
    }
}

// ---------------------------------------------------------------------------
// K_out2: partial[s][b][h] = F[:,352+s*1664 .. ] @ Up[s*1664.., :]
//   Tile 32b x 128h x 1664k, grid (64, 2), 256 thr, 4b x 4h per thread.
// ---------------------------------------------------------------------------
__global__ __launch_bounds__(256) void k_out2() {
    __shared__ float As[32][36];    // [kk][b]
    __shared__ float Ws[32][128];   // [kk][h]
    const int t = threadIdx.x;
    const int tx = t & 31;   // h = 4*tx
    const int ty = t >> 5;   // b = 4*ty + rb
    const int b0 = blockIdx.x * 32;
    const int s  = blockIdx.y;
    const int kbase = s * 1664;

    ull acc[4][2];
#pragma unroll
    for (int r = 0; r < 4; r++) { acc[r][0] = 0ULL; acc[r][1] = 0ULL; }

    for (int kc = 0; kc < 1664; kc += 32) {
        __syncthreads();
        {
            int row = t >> 3, c4 = t & 7;
            float4 v = *reinterpret_cast<const float4*>(
                g_F + (size_t)(b0 + row) * FSTR + 352 + kbase + kc + 4 * c4);
            As[4 * c4 + 0][row] = v.x;
            As[4 * c4 + 1][row] = v.y;
            As[4 * c4 + 2][row] = v.z;
            As[4 * c4 + 3][row] = v.w;
        }
#pragma unroll
        for (int l = 0; l < 4; l++) {
            int idx = t + 256 * l;
            int row = idx >> 5, c4 = idx & 31;
            reinterpret_cast<float4*>(&Ws[row][0])[c4] =
                reinterpret_cast<const float4*>(g_Up + (size_t)(kbase + kc + row) * 128)[c4];
        }
        __syncthreads();

#pragma unroll
        for (int kk = 0; kk < 32; kk++) {
            float4 a = *reinterpret_cast<const float4*>(&As[kk][4 * ty]);
            ulonglong2 w = *reinterpret_cast<const ulonglong2*>(&Ws[kk][4 * tx]);
            ull d;
            DUP2(d, a.x);
            FMA2(acc[0][0], w.x, d); FMA2(acc[0][1], w.y, d);
            DUP2(d, a.y);
            FMA2(acc[1][0], w.x, d); FMA2(acc[1][1], w.y, d);
            DUP2(d, a.z);
            FMA2(acc[2][0], w.x, d); FMA2(acc[2][1], w.y, d);
            DUP2(d, a.w);
            FMA2(acc[3][0], w.x, d); FMA2(acc[3][1], w.y, d);
        }
    }

    float* P = g_part[s];
#pragma unroll
    for (int r = 0; r < 4; r++) {
        float2 v0 = *reinterpret_cast<float2*>(&acc[r][0]);
        float2 v1 = *reinterpret_cast<float2*>(&acc[r][1]);
        float4 o; o.x = v0.x; o.y = v0.y; o.z = v1.x; o.w = v1.y;
        *reinterpret_cast<float4*>(P + (size_t)(b0 + 4 * ty + r) * 128 + 4 * tx) = o;
    }
}

// ---------------------------------------------------------------------------
// K_red: out[:,128:256] = part0 + part1 + 32*b2
// ---------------------------------------------------------------------------
__global__ void k_red(const float* __restrict__ b2, float* __restrict__ out) {
    int gid = blockIdx.x * blockDim.x + threadIdx.x;   // 2048*128
    int b = gid >> 7, h = gid & 127;
    out[(size_t)b * OUTW + 128 + h] = g_part[0][gid] + g_part[1][gid] + 32.f * b2[h];
}

// ---------------------------------------------------------------------------
extern "C" void kernel_launch(void* const* d_in, const int* in_sizes, int n_in,
                              void* d_out, int out_size) {
    const float* inputs = (const float*)d_in[0];  // [2048,26,32]
    const float* W1     = (const float*)d_in[1];  // [128,26,26]
    const float* b1     = (const float*)d_in[2];  // [128]
    const float* W2     = (const float*)d_in[3];  // [128,128,26]
    const float* b2     = (const float*)d_in[4];  // [128]
    float* out = (float*)d_out;                   // [2048,256]

    k_idx<<<1, 512>>>();
    k_w1s<<<(352 * 128) / 256, 256>>>(W1);
    k_w2t<<<(128 * NJ) / 256, 256>>>(W2);
    k_u<<<dim3(11, 52), 256>>>();
    k_fold<<<(NJ * 128) / 256, 256>>>(b1);
    k_feat<<<BATCH, 384>>>(inputs);
    k_out1<<<BATCH / 16, 256>>>(b1, out);
    k_out2<<<dim3(BATCH / 32, 2), 256>>>();
    k_red<<<(BATCH * 128) / 256, 256>>>(b2, out);
}